// round 9
// baseline (speedup 1.0000x reference)
#include <cuda_runtime.h>
#include <cstdint>

#define BB 64
#define TT 512
#define HH 768
#define KK 11
#define START_ID 9
#define END_ID 10
#define NEGV (-10000.0f)
#define NROWS (BB*TT)            // 32768

__device__ __align__(16) float g_feats[NROWS * KK];

// ---------------------------------------------------------------------------
// Kernel 1: feats[row][k] = dot(A[row,:], W[k,:]) + bias[k]   (DRAM roofline)
// ---------------------------------------------------------------------------
__global__ __launch_bounds__(256) void feats_kernel(
    const float* __restrict__ A,      // [NROWS, HH]
    const float* __restrict__ W,      // [KK, HH]
    const float* __restrict__ bias)   // [KK]
{
    __shared__ float sWt[HH * KK];    // [h*11 + k], 33792 B

    const int tid = threadIdx.x;
    for (int i = tid; i < HH * KK; i += 256) {
        int k = i / HH, h = i - k * HH;
        sWt[h * KK + k] = W[i];
    }
    __syncthreads();

    const int lane = tid & 31;
    const int warp = tid >> 5;
    const int rowBase = blockIdx.x * 32 + warp * 4;

    float acc[4][KK];
#pragma unroll
    for (int r = 0; r < 4; r++)
#pragma unroll
        for (int k = 0; k < KK; k++) acc[r][k] = 0.0f;

#pragma unroll
    for (int w = 0; w < 6; w++) {
        float a[4][4];
#pragma unroll
        for (int r = 0; r < 4; r++)
#pragma unroll
            for (int s = 0; s < 4; s++)
                a[r][s] = A[(size_t)(rowBase + r) * HH + w * 128 + s * 32 + lane];
#pragma unroll
        for (int s = 0; s < 4; s++) {
            float wr[KK];
            const int hb = (w * 128 + s * 32 + lane) * KK;
#pragma unroll
            for (int k = 0; k < KK; k++) wr[k] = sWt[hb + k];
#pragma unroll
            for (int r = 0; r < 4; r++)
#pragma unroll
                for (int k = 0; k < KK; k++)
                    acc[r][k] = fmaf(a[r][s], wr[k], acc[r][k]);
        }
    }

#pragma unroll
    for (int r = 0; r < 4; r++)
#pragma unroll
        for (int k = 0; k < KK; k++) {
            float v = acc[r][k];
            v += __shfl_xor_sync(0xffffffffu, v, 16);
            v += __shfl_xor_sync(0xffffffffu, v, 8);
            v += __shfl_xor_sync(0xffffffffu, v, 4);
            v += __shfl_xor_sync(0xffffffffu, v, 2);
            v += __shfl_xor_sync(0xffffffffu, v, 1);
            acc[r][k] = v;
        }

    if (lane == 0) {
#pragma unroll
        for (int r = 0; r < 4; r++)
#pragma unroll
            for (int k = 0; k < KK; k++)
                g_feats[(size_t)(rowBase + r) * KK + k] = acc[r][k] + __ldg(&bias[k]);
    }
}

// ---------------------------------------------------------------------------
// psi recompute: argmax_j (trans[tag][j] + delta[t-1][j]), first-max wins.
// Only j=0..8 can win for t>=2 (START/END predecessors masked to -1e4);
// at t=1 the winner is START for every target. Bit-exact vs reference.
// ---------------------------------------------------------------------------
__device__ __forceinline__ int psi_step(const float* __restrict__ strans,
                                        const float* __restrict__ sdelta,
                                        int t, int tag)
{
    if (t == 1) return START_ID;
    const float* tr = strans + tag * KK;
    const float* d = sdelta + (t - 1) * 12;
    float s[9];
#pragma unroll
    for (int j = 0; j < 9; j++) s[j] = tr[j] + d[j];
    float m = s[0];
#pragma unroll
    for (int j = 1; j < 9; j++) m = fmaxf(m, s[j]);
    unsigned msk = 0;
#pragma unroll
    for (int j = 0; j < 9; j++) msk |= (s[j] == m) ? (1u << j) : 0u;
    return __ffs(msk) - 1;
}

// ---------------------------------------------------------------------------
// Kernel 2: Viterbi. One block per batch.
// Scan (warp 0): 9 live predecessors; targets 0..8 on lanes 0..8, END on
// lanes 9..31 (stored in slot 9). Transport: d0..d7 via STS + 2x LDS.128
// with immediate offsets; d8 via SHFL.IDX from lane 8 (issued early, arrives
// before the LDS). t=1 closed-form. Backtrack recomputes psi (exact).
// ---------------------------------------------------------------------------
__global__ __launch_bounds__(192) void viterbi_kernel(
    const float* __restrict__ trans,   // [KK, KK]
    float* __restrict__ out)           // [BB + BB*TT]
{
    const int b = blockIdx.x;
    const int tid = threadIdx.x;

    __shared__ float sfeat[(TT + 8) * KK];            // 22880 B (pad rows)
    __shared__ __align__(16) float sdelta[TT * 12];   // 24576 B, [t*12 + slot]
    __shared__ float strans[KK * KK];                 // 484 B
    __shared__ unsigned char s_pathseg[16][KK][32];   // 5632 B
    __shared__ unsigned char s_esel[16];
    __shared__ int s_lasttag;
    __shared__ float s_score;

    // stage this batch's feats + transitions
    {
        const float4* f4 = reinterpret_cast<const float4*>(g_feats + (size_t)b * TT * KK);
        float4* s4 = reinterpret_cast<float4*>(sfeat);
        for (int i = tid; i < (TT * KK) / 4; i += 192) s4[i] = f4[i];
    }
    for (int i = tid; i < KK * KK; i += 192) strans[i] = trans[i];
    __syncthreads();

    if (tid < 32) {
        const int lane = tid;
        const int target = (lane <= 8) ? lane : END_ID;       // lanes 9..31 -> END
        const int slot4 = ((lane <= 8) ? lane : 9) * 4;       // END in slot 9

        float tr0 = strans[target * KK + 0], tr1 = strans[target * KK + 1];
        float tr2 = strans[target * KK + 2], tr3 = strans[target * KK + 3];
        float tr4 = strans[target * KK + 4], tr5 = strans[target * KK + 5];
        float tr6 = strans[target * KK + 6], tr7 = strans[target * KK + 7];
        float tr8 = strans[target * KK + 8], tr9 = strans[target * KK + 9];

        const unsigned sd_base = (unsigned)__cvta_generic_to_shared(sdelta);

        float d0, d1, d2, d3, d4, d5, d6, d7, d8;

        // ---- t = 1 closed form: predecessor is START (certain) ----
        {
            float nd1 = (tr9 + 0.0f) + sfeat[KK + target];
            unsigned row1 = sd_base + 48;
            asm volatile("st.shared.f32 [%0], %1;"
                         :: "r"(row1 + slot4), "f"(nd1) : "memory");
            d8 = __shfl_sync(0xffffffffu, nd1, 8);
            asm volatile("ld.shared.v4.f32 {%0,%1,%2,%3}, [%4];"
                         : "=f"(d0), "=f"(d1), "=f"(d2), "=f"(d3)
                         : "r"(row1) : "memory");
            asm volatile("ld.shared.v4.f32 {%0,%1,%2,%3}, [%4+16];"
                         : "=f"(d4), "=f"(d5), "=f"(d6), "=f"(d7)
                         : "r"(row1) : "memory");
        }

        float fbuf[6];
#pragma unroll
        for (int s = 0; s < 6; s++) fbuf[s] = sfeat[(2 + s) * KK + target];
        const float* fpre = sfeat + 8 * KK + target;

        unsigned addr = sd_base + 96;              // row 2 (written by U_=0)
        unsigned sd_store = addr + slot4;

#define VSTEP(U_, O0, O1)                                                      \
        {                                                                      \
            float f = fbuf[U_];                                                \
            fbuf[U_] = *fpre; fpre += KK;                                      \
            float s0 = tr0 + d0, s1 = tr1 + d1, s2 = tr2 + d2, s3 = tr3 + d3;  \
            float s4 = tr4 + d4, s5 = tr5 + d5, s6 = tr6 + d6, s7 = tr7 + d7;  \
            float s8v = tr8 + d8;                                              \
            float m01 = fmaxf(s0, s1), m23 = fmaxf(s2, s3);                    \
            float m45 = fmaxf(s4, s5), m67 = fmaxf(s6, s7);                    \
            float m = fmaxf(fmaxf(fmaxf(m01, m23), fmaxf(m45, m67)), s8v);     \
            float nd = m + f;                                                  \
            d8 = __shfl_sync(0xffffffffu, nd, 8);                              \
            asm volatile("st.shared.f32 [%0+" #O0 "], %1;"                     \
                         :: "r"(sd_store), "f"(nd) : "memory");                \
            asm volatile("ld.shared.v4.f32 {%0,%1,%2,%3}, [%4+" #O0 "];"       \
                         : "=f"(d0), "=f"(d1), "=f"(d2), "=f"(d3)              \
                         : "r"(addr) : "memory");                              \
            asm volatile("ld.shared.v4.f32 {%0,%1,%2,%3}, [%4+" #O1 "];"       \
                         : "=f"(d4), "=f"(d5), "=f"(d6), "=f"(d7)              \
                         : "r"(addr) : "memory");                              \
        }

        for (int it = 0; it < 85; ++it) {       // 85 * 6 = 510 steps, t = 2..511
            VSTEP(0, 0, 16)
            VSTEP(1, 48, 64)
            VSTEP(2, 96, 112)
            VSTEP(3, 144, 160)
            VSTEP(4, 192, 208)
            VSTEP(5, 240, 256)
            addr += 288;
            sd_store += 288;
        }
#undef VSTEP

        __syncwarp();
        // d0..d8 = live deltas at t=511; END delta in slot 9 of row 511
        float dEND = sdelta[511 * 12 + 9];

        {
            float m01 = fmaxf(d0, d1), m23 = fmaxf(d2, d3);
            float m45 = fmaxf(d4, d5), m67 = fmaxf(d6, d7);
            float m = fmaxf(fmaxf(fmaxf(m01, m23), fmaxf(m45, m67)),
                            fmaxf(d8, dEND));
            unsigned msk = (d0 == m ? 1u : 0u) | (d1 == m ? 2u : 0u) |
                           (d2 == m ? 4u : 0u) | (d3 == m ? 8u : 0u) |
                           (d4 == m ? 16u : 0u) | (d5 == m ? 32u : 0u) |
                           (d6 == m ? 64u : 0u) | (d7 == m ? 128u : 0u) |
                           (d8 == m ? 256u : 0u) |
                           (dEND == m ? (1u << END_ID) : 0u);
            if (lane == 0) {
                s_score = m;
                s_lasttag = __ffs(msk) - 1;
            }
        }
    }
    __syncthreads();

    // ---- chunked backtrack, psi recomputed from stored deltas ----
    if (tid < 165) {                       // chunks 0..14 x 11 entry tags
        const int c = tid / KK;
        const int e = tid - c * KK;
        const int tb = 32 * c;
        int tag = e;                       // candidate tag at position tb+32
        for (int t = tb + 32; t > tb; --t) {
            tag = psi_step(strans, sdelta, t, tag);
            s_pathseg[c][e][t - 1 - tb] = (unsigned char)tag;
        }
    } else if (tid == 165) {               // chunk 15 from known last tag
        int tag = s_lasttag;
        s_pathseg[15][0][31] = (unsigned char)tag;
        for (int t = TT - 1; t > 480; --t) {
            tag = psi_step(strans, sdelta, t, tag);
            s_pathseg[15][0][t - 1 - 480] = (unsigned char)tag;
        }
    }
    __syncthreads();

    if (tid == 0) {
        s_esel[15] = 0;
        int btag = s_pathseg[15][0][0];    // tag at position 480
        for (int c = 14; c >= 0; --c) {
            s_esel[c] = (unsigned char)btag;
            btag = s_pathseg[c][btag][0];  // tag at position 32c
        }
    }
    __syncthreads();

    if (tid == 0) out[b] = s_score;
    for (int p = tid; p < TT; p += 192) {
        int c = p >> 5;
        out[BB + (size_t)b * TT + p] = (float)s_pathseg[c][s_esel[c]][p & 31];
    }
}

// ---------------------------------------------------------------------------
extern "C" void kernel_launch(void* const* d_in, const int* in_sizes, int n_in,
                              void* d_out, int out_size)
{
    const float* embeds = (const float*)d_in[0];   // [B,T,H]
    const float* W_fc   = (const float*)d_in[1];   // [K,H]
    const float* b_fc   = (const float*)d_in[2];   // [K]
    const float* trans  = (const float*)d_in[3];   // [K,K]
    float* out = (float*)d_out;

    feats_kernel<<<1024, 256>>>(embeds, W_fc, b_fc);
    viterbi_kernel<<<BB, 192>>>(trans, out);
}